// round 15
// baseline (speedup 1.0000x reference)
#include <cuda_runtime.h>
#include <cuda_bf16.h>
#include <cstdint>

// Problem constants
#define B_    8
#define N_    1024
#define FIN   256
#define NH    8
#define ND    32
#define M_TOT (B_ * N_)      // 8192
#define NBH   (B_ * NH)      // 64
#define ROWS  1025
#define OCOLS (NH * ND)      // 256

// ---------------- scratch ----------------
__device__ float g_buf[M_TOT * OCOLS];
__device__ float ssrc_buf[NBH * N_];
__device__ float sdst_buf[NBH * N_];
__device__ int   sid_buf[NBH * N_];
__device__ float e1_buf[NBH * N_];
__device__ float e2_buf[NBH * N_];
__device__ float suf1_buf[NBH * ROWS * ND];
__device__ float pre2_buf[NBH * ROWS * ND];
__device__ float cb1_buf[NBH * 32 * 32];
__device__ float cb2_buf[NBH * 32 * 32];
__device__ float4 qscal_buf[NBH * N_];        // {E1/den, E2/den, bits(t), 0}
__device__ __nv_bfloat16 Wth_buf[OCOLS * FIN];  // W^T hi  [n][k]
__device__ __nv_bfloat16 Wtl_buf[OCOLS * FIN];  // W^T lo  [n][k]

// ---------------- helpers ----------------
#define MMA_BF16(d, a, b)                                                      \
    asm volatile("mma.sync.aligned.m16n8k16.row.col.f32.bf16.bf16.f32 "        \
        "{%0,%1,%2,%3}, {%4,%5,%6,%7}, {%8,%9}, {%0,%1,%2,%3};"                \
        : "+f"((d)[0]), "+f"((d)[1]), "+f"((d)[2]), "+f"((d)[3])               \
        : "r"((a)[0]), "r"((a)[1]), "r"((a)[2]), "r"((a)[3]),                  \
          "r"((b)[0]), "r"((b)[1]))

__device__ __forceinline__ void ldsm4(uint32_t& r0, uint32_t& r1, uint32_t& r2,
                                      uint32_t& r3, uint32_t a) {
    asm volatile("ldmatrix.sync.aligned.m8n8.x4.shared.b16 {%0,%1,%2,%3}, [%4];"
                 : "=r"(r0), "=r"(r1), "=r"(r2), "=r"(r3) : "r"(a));
}

// ---------------- kernel 0: W[k][n] fp32 -> Wt hi/lo [n][k] bf16 ----------------
__global__ __launch_bounds__(256) void trans_k(const float* __restrict__ W) {
    __shared__ float ts[32][33];
    int tk = (blockIdx.x & 7) * 32;
    int tn = (blockIdx.x >> 3) * 32;
    int r = threadIdx.x >> 5, c = threadIdx.x & 31;
#pragma unroll
    for (int j = 0; j < 4; j++)
        ts[r + j * 8][c] = W[(size_t)(tk + r + j * 8) * OCOLS + tn + c];
    __syncthreads();
#pragma unroll
    for (int j = 0; j < 4; j++) {
        int n = r + j * 8;
        float x = ts[c][n];
        __nv_bfloat16 h = __float2bfloat16(x);
        Wth_buf[(size_t)(tn + n) * FIN + tk + c] = h;
        Wtl_buf[(size_t)(tn + n) * FIN + tk + c] =
            __float2bfloat16(x - __bfloat162float(h));
    }
}

// ---------------- kernel 1: GEMM via HMMA + LDSM, packed bf16x2 staging ----------------
#define SA 40
__global__ __launch_bounds__(256) void gemm_mma_k(const float* __restrict__ A,
                                                  const float* __restrict__ attn_w) {
    __shared__ __align__(16) __nv_bfloat16 Ah[64 * SA];
    __shared__ __align__(16) __nv_bfloat16 Al[64 * SA];
    __shared__ __align__(16) __nv_bfloat16 Bh[128 * SA];
    __shared__ __align__(16) __nv_bfloat16 Bl[128 * SA];

    const int tid = threadIdx.x;
    const int wid = tid >> 5, lane = tid & 31;
    const int wm = wid >> 2, wn = wid & 3;
    const int rowBase = blockIdx.y * 64;
    const int colBase = blockIdx.x * 128;
    const int g = lane >> 2, tg = lane & 3;

    const int ar0 = tid >> 3, ac4 = (tid & 7) << 2;
    const int br = tid >> 2, bc = tid & 3;

    const uint32_t sAh = (uint32_t)__cvta_generic_to_shared(Ah);
    const uint32_t sAl = (uint32_t)__cvta_generic_to_shared(Al);
    const uint32_t sBh = (uint32_t)__cvta_generic_to_shared(Bh);
    const uint32_t sBl = (uint32_t)__cvta_generic_to_shared(Bl);

    const uint32_t aoff = (uint32_t)(((lane & 15) * SA + ((lane >> 4) << 3)) * 2);
    const uint32_t boff = (uint32_t)((((lane & 7) + ((lane >> 4) << 3)) * SA
                                      + (((lane >> 3) & 1) << 3)) * 2);

    float acc[2][4][4];
#pragma unroll
    for (int mt = 0; mt < 2; mt++)
#pragma unroll
        for (int nt = 0; nt < 4; nt++)
#pragma unroll
            for (int r = 0; r < 4; r++) acc[mt][nt][r] = 0.f;

    const uint4* Wth4 = (const uint4*)Wth_buf;
    const uint4* Wtl4 = (const uint4*)Wtl_buf;

    float4 pa[2]; uint4 pbh[2], pbl[2];
    pa[0] = *(const float4*)(A + (size_t)(rowBase + ar0) * FIN + ac4);
    pa[1] = *(const float4*)(A + (size_t)(rowBase + ar0 + 32) * FIN + ac4);
#pragma unroll
    for (int it = 0; it < 2; it++) {
        int row = br + it * 64;
        pbh[it] = Wth4[(size_t)(colBase + row) * 32 + bc];
        pbl[it] = Wtl4[(size_t)(colBase + row) * 32 + bc];
    }

    for (int kc = 0; kc < 8; kc++) {
        __syncthreads();
        // stage A: packed bf16x2 hi/lo, 8-byte stores
#pragma unroll
        for (int it = 0; it < 2; it++) {
            int r = ar0 + it * 32;
            float4 v = pa[it];
            __nv_bfloat162 h01 = __floats2bfloat162_rn(v.x, v.y);
            __nv_bfloat162 h23 = __floats2bfloat162_rn(v.z, v.w);
            float2 f01 = __bfloat1622float2(h01);
            float2 f23 = __bfloat1622float2(h23);
            __nv_bfloat162 l01 = __floats2bfloat162_rn(v.x - f01.x, v.y - f01.y);
            __nv_bfloat162 l23 = __floats2bfloat162_rn(v.z - f23.x, v.w - f23.y);
            uint2 hp, lp;
            hp.x = *(uint32_t*)&h01; hp.y = *(uint32_t*)&h23;
            lp.x = *(uint32_t*)&l01; lp.y = *(uint32_t*)&l23;
            *(uint2*)&Ah[r * SA + ac4] = hp;
            *(uint2*)&Al[r * SA + ac4] = lp;
        }
        // stage B (already bf16, 16B row stores)
#pragma unroll
        for (int it = 0; it < 2; it++) {
            int row = br + it * 64;
            *(uint4*)&Bh[row * SA + bc * 8] = pbh[it];
            *(uint4*)&Bl[row * SA + bc * 8] = pbl[it];
        }
        __syncthreads();

        if (kc < 7) {
            int k0 = (kc + 1) * 32;
            pa[0] = *(const float4*)(A + (size_t)(rowBase + ar0) * FIN + k0 + ac4);
            pa[1] = *(const float4*)(A + (size_t)(rowBase + ar0 + 32) * FIN + k0 + ac4);
#pragma unroll
            for (int it = 0; it < 2; it++) {
                int row = br + it * 64;
                pbh[it] = Wth4[(size_t)(colBase + row) * 32 + (kc + 1) * 4 + bc];
                pbl[it] = Wtl4[(size_t)(colBase + row) * 32 + (kc + 1) * 4 + bc];
            }
        }

#pragma unroll
        for (int ks = 0; ks < 2; ks++) {
            const uint32_t kb = (uint32_t)(ks * 16 * 2);
            uint32_t ah[2][4], al[2][4], bb[4][2];
#pragma unroll
            for (int mt = 0; mt < 2; mt++) {
                uint32_t ro = (uint32_t)((wm * 32 + mt * 16) * SA * 2);
                ldsm4(ah[mt][0], ah[mt][1], ah[mt][2], ah[mt][3], sAh + aoff + ro + kb);
                ldsm4(al[mt][0], al[mt][1], al[mt][2], al[mt][3], sAl + aoff + ro + kb);
            }
#pragma unroll
            for (int p = 0; p < 2; p++) {
                uint32_t ro = (uint32_t)((wn * 32 + p * 16) * SA * 2);
                ldsm4(bb[2 * p][0], bb[2 * p][1], bb[2 * p + 1][0], bb[2 * p + 1][1],
                      sBh + boff + ro + kb);
            }
#pragma unroll
            for (int mt = 0; mt < 2; mt++)
#pragma unroll
                for (int nt = 0; nt < 4; nt++) {
                    MMA_BF16(acc[mt][nt], ah[mt], bb[nt]);
                    MMA_BF16(acc[mt][nt], al[mt], bb[nt]);
                }
#pragma unroll
            for (int p = 0; p < 2; p++) {
                uint32_t ro = (uint32_t)((wn * 32 + p * 16) * SA * 2);
                ldsm4(bb[2 * p][0], bb[2 * p][1], bb[2 * p + 1][0], bb[2 * p + 1][1],
                      sBl + boff + ro + kb);
            }
#pragma unroll
            for (int mt = 0; mt < 2; mt++)
#pragma unroll
                for (int nt = 0; nt < 4; nt++)
                    MMA_BF16(acc[mt][nt], ah[mt], bb[nt]);
        }
    }

#pragma unroll
    for (int mt = 0; mt < 2; mt++) {
        int r0 = rowBase + wm * 32 + mt * 16 + g;
#pragma unroll
        for (int nt = 0; nt < 4; nt++) {
            int c0 = colBase + wn * 32 + nt * 8 + tg * 2;
            *(float2*)(g_buf + (size_t)r0 * OCOLS + c0) =
                make_float2(acc[mt][nt][0], acc[mt][nt][1]);
            *(float2*)(g_buf + (size_t)(r0 + 8) * OCOLS + c0) =
                make_float2(acc[mt][nt][2], acc[mt][nt][3]);
        }
    }

    // fused score
    {
        float ws[4][2], wd[4][2];
#pragma unroll
        for (int nt = 0; nt < 4; nt++)
#pragma unroll
            for (int j = 0; j < 2; j++) {
                int d = nt * 8 + tg * 2 + j;
                ws[nt][j] = attn_w[d];
                wd[nt][j] = attn_w[32 + d];
            }
        int hh = blockIdx.x * 4 + wn;
#pragma unroll
        for (int mt = 0; mt < 2; mt++)
#pragma unroll
            for (int rh = 0; rh < 2; rh++) {
                float as = 0.f, ad = 0.f;
#pragma unroll
                for (int nt = 0; nt < 4; nt++) {
                    as += acc[mt][nt][rh * 2] * ws[nt][0] + acc[mt][nt][rh * 2 + 1] * ws[nt][1];
                    ad += acc[mt][nt][rh * 2] * wd[nt][0] + acc[mt][nt][rh * 2 + 1] * wd[nt][1];
                }
                as += __shfl_xor_sync(0xffffffffu, as, 1);
                as += __shfl_xor_sync(0xffffffffu, as, 2);
                ad += __shfl_xor_sync(0xffffffffu, ad, 1);
                ad += __shfl_xor_sync(0xffffffffu, ad, 2);
                if (tg == 0) {
                    int m = rowBase + wm * 32 + mt * 16 + rh * 8 + g;
                    int b = m >> 10, i = m & 1023;
                    ssrc_buf[(size_t)(b * NH + hh) * N_ + i] = as;
                    sdst_buf[(size_t)(b * NH + hh) * N_ + i] = ad;
                }
            }
    }
}

// ---------------- kernel 2: sort + scans + chunk bases + fused query scalars ----------------
__device__ __forceinline__ void warp_passes_u(uint32_t& key, int k, int jmax, int tid) {
    for (int j = jmax; j > 0; j >>= 1) {
        uint32_t pk = __shfl_xor_sync(0xffffffffu, key, j);
        bool lower = ((tid & j) == 0);
        bool up = ((tid & k) == 0);
        bool keepmin = (lower == up);
        bool sw = keepmin ? (key > pk) : (key < pk);
        if (sw) key = pk;
    }
}

__global__ __launch_bounds__(1024) void prep_k() {
    __shared__ uint32_t su[1024];
    __shared__ float vs[1024];
    __shared__ float e1s[1024];
    __shared__ float e2s[1024];
    __shared__ float sc1[ROWS];
    __shared__ float sc2[ROWS];
    __shared__ float wt[32], wo[32], wt2[32], wo2[32];
    __shared__ float tot1[32][33];
    __shared__ float tot2[32][33];

    int bh = blockIdx.x;
    int b = bh >> 3, h = bh & 7;
    int tid = threadIdx.x;
    int w = tid >> 5, lane = tid & 31;

    float v0 = sdst_buf[(size_t)bh * N_ + tid];
    uint32_t u = __float_as_uint(v0);
    u = (u & 0x80000000u) ? ~u : (u | 0x80000000u);
    uint32_t key = (u & 0xFFFFFC00u) | (uint32_t)tid;

#pragma unroll
    for (int k = 2; k <= 32; k <<= 1) warp_passes_u(key, k, k >> 1, tid);
    su[tid] = key;
    __syncthreads();
    for (int k = 64; k <= 1024; k <<= 1) {
        for (int j = k >> 1; j >= 32; j >>= 1) {
            int ixj = tid ^ j;
            if (ixj > tid) {
                bool up = ((tid & k) == 0);
                uint32_t a = su[tid], c = su[ixj];
                bool sw = up ? (a > c) : (a < c);
                if (sw) { su[tid] = c; su[ixj] = a; }
            }
            __syncthreads();
        }
        key = su[tid];
        warp_passes_u(key, k, 16, tid);
        su[tid] = key;
        __syncthreads();
    }

    int idj = (int)(key & 1023u);
    float rv = sdst_buf[(size_t)bh * N_ + idj];
    vs[tid] = rv;
    sid_buf[(size_t)bh * N_ + tid] = idj;
    float x1 = __expf(rv);
    float x2 = __expf(0.2f * rv);
    e1s[tid] = x1; e2s[tid] = x2;
    e1_buf[(size_t)bh * N_ + tid] = x1;
    e2_buf[(size_t)bh * N_ + tid] = x2;

    float s2 = x2;
#pragma unroll
    for (int o = 1; o < 32; o <<= 1) {
        float y = __shfl_up_sync(0xffffffffu, s2, o);
        if (lane >= o) s2 += y;
    }
    if (lane == 31) wt2[w] = s2;
    float s1 = x1;
#pragma unroll
    for (int o = 1; o < 32; o <<= 1) {
        float y = __shfl_down_sync(0xffffffffu, s1, o);
        if (lane + o < 32) s1 += y;
    }
    if (lane == 0) wt[w] = s1;
    __syncthreads();
    if (w == 0) {
        float t = wt[lane];
        float ts = t;
#pragma unroll
        for (int o = 1; o < 32; o <<= 1) {
            float y = __shfl_down_sync(0xffffffffu, ts, o);
            if (lane + o < 32) ts += y;
        }
        wo[lane] = ts - t;
        float t2 = wt2[lane];
        float ps = t2;
#pragma unroll
        for (int o = 1; o < 32; o <<= 1) {
            float y = __shfl_up_sync(0xffffffffu, ps, o);
            if (lane >= o) ps += y;
        }
        wo2[lane] = ps - t2;
    }
    __syncthreads();
    sc1[tid] = s1 + wo[w];
    sc2[tid + 1] = s2 + wo2[w];
    if (tid == 0) {
        sc1[1024] = 0.f;
        sc2[0] = 0.f;
    }
    __syncthreads();

    // fused per-query scalars
    {
        float src = ssrc_buf[(size_t)bh * N_ + tid];
        float th = -src;
        int lo = 0, hi = 1024;
#pragma unroll
        for (int s = 0; s < 10; s++) {
            int mid = (lo + hi) >> 1;
            if (vs[mid] < th) lo = mid + 1; else hi = mid;
        }
        int t = lo;
        float vmax = vs[1023];
        float etop = src + vmax;
        float mM = (etop >= 0.f) ? etop : 0.2f * etop;
        float E1 = (t < 1024) ? __expf(src - mM) : 0.f;
        float E2 = (t > 0) ? __expf(0.2f * src - mM) : 0.f;
        float rden = 1.f / (E1 * sc1[t] + E2 * sc2[t]);
        qscal_buf[(size_t)bh * N_ + tid] =
            make_float4(E1 * rden, E2 * rden, __int_as_float(t), 0.f);
    }

    // vector chunk totals (prefetched)
    const float* gb = g_buf + (size_t)b * N_ * OCOLS + h * ND;
    float t1 = 0.f, t2v = 0.f;
#pragma unroll
    for (int half = 0; half < 2; half++) {
        float gv[16];
#pragma unroll
        for (int kk = 0; kk < 16; kk++) {
            int k = (w << 5) + half * 16 + kk;
            int j = (int)(su[k] & 1023u);
            gv[kk] = gb[(size_t)j * OCOLS + lane];
        }
#pragma unroll
        for (int kk = 0; kk < 16; kk++) {
            int k = (w << 5) + half * 16 + kk;
            t1 = fmaf(e1s[k], gv[kk], t1);
            t2v = fmaf(e2s[k], gv[kk], t2v);
        }
    }
    tot1[w][lane] = t1;
    tot2[w][lane] = t2v;
    __syncthreads();
    {
        float a1 = tot1[lane][w];
        float a2 = tot2[lane][w];
        float inc1 = a1;
#pragma unroll
        for (int o = 1; o < 32; o <<= 1) {
            float y = __shfl_down_sync(0xffffffffu, inc1, o);
            if (lane + o < 32) inc1 += y;
        }
        float inc2 = a2;
#pragma unroll
        for (int o = 1; o < 32; o <<= 1) {
            float y = __shfl_up_sync(0xffffffffu, inc2, o);
            if (lane >= o) inc2 += y;
        }
        cb1_buf[((size_t)bh * 32 + lane) * 32 + w] = inc1;
        cb2_buf[((size_t)bh * 32 + lane) * 32 + w] = inc2 - a2;
    }
}

// ---------------- kernel 3: merged prefix/suffix writes (quarter split) ----------------
// grid (16, 64), 256 threads = 8 warps = 2 chunks x 4 quarters of 8 positions.
__global__ __launch_bounds__(256) void write_k() {
    __shared__ float qs1[2][4][32];
    __shared__ float qs2[2][4][32];

    int bh = blockIdx.y;
    int b = bh >> 3, h = bh & 7;
    int w = threadIdx.x >> 5, lane = threadIdx.x & 31;
    int j = w >> 2, q = w & 3;
    int c = blockIdx.x * 2 + j;
    int k0 = (c << 5) + q * 8;

    const float* gb = g_buf + (size_t)b * N_ * OCOLS + h * ND;
    const int* sidp = sid_buf + (size_t)bh * N_ + k0;
    const float* e1p = e1_buf + (size_t)bh * N_ + k0;
    const float* e2p = e2_buf + (size_t)bh * N_ + k0;
    float* S1 = suf1_buf + (size_t)bh * ROWS * ND;
    float* P2 = pre2_buf + (size_t)bh * ROWS * ND;

    // prefetch 8 gathers + e factors
    float gv[8], ee1[8], ee2[8];
#pragma unroll
    for (int kk = 0; kk < 8; kk++) {
        gv[kk] = gb[(size_t)sidp[kk] * OCOLS + lane];
        ee1[kk] = e1p[kk];
        ee2[kk] = e2p[kk];
    }

    // publish quarter sums
    {
        float l1 = 0.f, l2 = 0.f;
#pragma unroll
        for (int kk = 0; kk < 8; kk++) {
            l1 = fmaf(ee1[kk], gv[kk], l1);
            l2 = fmaf(ee2[kk], gv[kk], l2);
        }
        qs1[j][q][lane] = l1;
        qs2[j][q][lane] = l2;
    }
    __syncthreads();

    float is1 = cb1_buf[((size_t)bh * 32 + c) * 32 + lane];
    float base2 = cb2_buf[((size_t)bh * 32 + c) * 32 + lane];
    float p1 = 0.f, pre = 0.f;
#pragma unroll
    for (int qq = 0; qq < 3; qq++) {
        if (qq < q) {
            p1 += qs1[j][qq][lane];
            pre += qs2[j][qq][lane];
        }
    }
    float r2 = base2 + pre;

    if (c == 0 && q == 0) P2[lane] = 0.f;

#pragma unroll
    for (int kk = 0; kk < 8; kk++) {
        int k = k0 + kk;
        S1[(size_t)k * ND + lane] = is1 - p1;
        p1 = fmaf(ee1[kk], gv[kk], p1);
        r2 = fmaf(ee2[kk], gv[kk], r2);
        P2[(size_t)(k + 1) * ND + lane] = r2;
    }
    if (c == 31 && q == 3) S1[(size_t)1024 * ND + lane] = 0.f;
}

// ---------------- kernel 4: output (4 independent float4 per thread) ----------------
__global__ __launch_bounds__(256) void out_k(float* __restrict__ out) {
    int idx = blockIdx.x * 256 + threadIdx.x;      // 128K threads
#pragma unroll
    for (int q = 0; q < 4; q++) {
        int e = (idx + q * 131072) << 2;           // four quarters of 2M floats
        int m = e >> 8, cc = e & 255;
        int h = cc >> 5, d0 = cc & 31;
        int b = m >> 10, i = m & 1023;
        int bh = b * NH + h;
        float4 s = qscal_buf[(size_t)bh * N_ + i];
        int t = __float_as_int(s.z);
        size_t base = ((size_t)bh * ROWS + t) * ND + d0;
        float4 sf = *(const float4*)(suf1_buf + base);
        float4 pf = *(const float4*)(pre2_buf + base);
        float4 o;
        o.x = s.x * sf.x + s.y * pf.x;
        o.y = s.x * sf.y + s.y * pf.y;
        o.z = s.x * sf.z + s.y * pf.z;
        o.w = s.x * sf.w + s.y * pf.w;
        *(float4*)(out + e) = o;
    }
}

// ---------------- launcher ----------------
extern "C" void kernel_launch(void* const* d_in, const int* in_sizes, int n_in,
                              void* d_out, int out_size) {
    const float* vertex = (const float*)d_in[0];
    const float* w_vert = (const float*)d_in[1];
    const float* attn_w = (const float*)d_in[2];
    float* out = (float*)d_out;

    trans_k<<<64, 256>>>(w_vert);
    dim3 gG(2, 128);
    gemm_mma_k<<<gG, 256>>>(vertex, attn_w);
    prep_k<<<NBH, 1024>>>();
    write_k<<<dim3(16, NBH), 256>>>();
    out_k<<<M_TOT * OCOLS / 16 / 256, 256>>>(out);
}

// round 16
// speedup vs baseline: 1.0394x; 1.0394x over previous
#include <cuda_runtime.h>
#include <cuda_bf16.h>
#include <cstdint>

// Problem constants
#define B_    8
#define N_    1024
#define FIN   256
#define NH    8
#define ND    32
#define M_TOT (B_ * N_)      // 8192
#define NBH   (B_ * NH)      // 64
#define ROWS  1025
#define OCOLS (NH * ND)      // 256

// ---------------- scratch ----------------
__device__ float g_buf[M_TOT * OCOLS];
__device__ float ssrc_buf[NBH * N_];
__device__ float sdst_buf[NBH * N_];
__device__ float suf1_buf[NBH * ROWS * ND];
__device__ float pre2_buf[NBH * ROWS * ND];
__device__ __nv_bfloat16 Wth_buf[OCOLS * FIN];  // W^T hi  [n][k]
__device__ __nv_bfloat16 Wtl_buf[OCOLS * FIN];  // W^T lo  [n][k]

// ---------------- helpers ----------------
#define MMA_BF16(d, a, b)                                                      \
    asm volatile("mma.sync.aligned.m16n8k16.row.col.f32.bf16.bf16.f32 "        \
        "{%0,%1,%2,%3}, {%4,%5,%6,%7}, {%8,%9}, {%0,%1,%2,%3};"                \
        : "+f"((d)[0]), "+f"((d)[1]), "+f"((d)[2]), "+f"((d)[3])               \
        : "r"((a)[0]), "r"((a)[1]), "r"((a)[2]), "r"((a)[3]),                  \
          "r"((b)[0]), "r"((b)[1]))

__device__ __forceinline__ void ldsm4(uint32_t& r0, uint32_t& r1, uint32_t& r2,
                                      uint32_t& r3, uint32_t a) {
    asm volatile("ldmatrix.sync.aligned.m8n8.x4.shared.b16 {%0,%1,%2,%3}, [%4];"
                 : "=r"(r0), "=r"(r1), "=r"(r2), "=r"(r3) : "r"(a));
}

// ---------------- kernel 0: W[k][n] fp32 -> Wt hi/lo [n][k] bf16 ----------------
__global__ __launch_bounds__(256) void trans_k(const float* __restrict__ W) {
    __shared__ float ts[32][33];
    int tk = (blockIdx.x & 7) * 32;
    int tn = (blockIdx.x >> 3) * 32;
    int r = threadIdx.x >> 5, c = threadIdx.x & 31;
#pragma unroll
    for (int j = 0; j < 4; j++)
        ts[r + j * 8][c] = W[(size_t)(tk + r + j * 8) * OCOLS + tn + c];
    __syncthreads();
#pragma unroll
    for (int j = 0; j < 4; j++) {
        int n = r + j * 8;
        float x = ts[c][n];
        __nv_bfloat16 h = __float2bfloat16(x);
        Wth_buf[(size_t)(tn + n) * FIN + tk + c] = h;
        Wtl_buf[(size_t)(tn + n) * FIN + tk + c] =
            __float2bfloat16(x - __bfloat162float(h));
    }
}

// ---------------- kernel 1: GEMM via HMMA + LDSM (R14 version) ----------------
#define SA 40
__global__ __launch_bounds__(256) void gemm_mma_k(const float* __restrict__ A,
                                                  const float* __restrict__ attn_w) {
    __shared__ __align__(16) __nv_bfloat16 Ah[64 * SA];
    __shared__ __align__(16) __nv_bfloat16 Al[64 * SA];
    __shared__ __align__(16) __nv_bfloat16 Bh[128 * SA];
    __shared__ __align__(16) __nv_bfloat16 Bl[128 * SA];

    const int tid = threadIdx.x;
    const int wid = tid >> 5, lane = tid & 31;
    const int wm = wid >> 2, wn = wid & 3;
    const int rowBase = blockIdx.y * 64;
    const int colBase = blockIdx.x * 128;
    const int g = lane >> 2, tg = lane & 3;

    const int ar0 = tid >> 3, ac4 = (tid & 7) << 2;
    const int br = tid >> 2, bc = tid & 3;

    const uint32_t sAh = (uint32_t)__cvta_generic_to_shared(Ah);
    const uint32_t sAl = (uint32_t)__cvta_generic_to_shared(Al);
    const uint32_t sBh = (uint32_t)__cvta_generic_to_shared(Bh);
    const uint32_t sBl = (uint32_t)__cvta_generic_to_shared(Bl);

    const uint32_t aoff = (uint32_t)(((lane & 15) * SA + ((lane >> 4) << 3)) * 2);
    const uint32_t boff = (uint32_t)((((lane & 7) + ((lane >> 4) << 3)) * SA
                                      + (((lane >> 3) & 1) << 3)) * 2);

    float acc[2][4][4];
#pragma unroll
    for (int mt = 0; mt < 2; mt++)
#pragma unroll
        for (int nt = 0; nt < 4; nt++)
#pragma unroll
            for (int r = 0; r < 4; r++) acc[mt][nt][r] = 0.f;

    const uint4* Wth4 = (const uint4*)Wth_buf;
    const uint4* Wtl4 = (const uint4*)Wtl_buf;

    float4 pa[2]; uint4 pbh[2], pbl[2];
    pa[0] = *(const float4*)(A + (size_t)(rowBase + ar0) * FIN + ac4);
    pa[1] = *(const float4*)(A + (size_t)(rowBase + ar0 + 32) * FIN + ac4);
#pragma unroll
    for (int it = 0; it < 2; it++) {
        int row = br + it * 64;
        pbh[it] = Wth4[(size_t)(colBase + row) * 32 + bc];
        pbl[it] = Wtl4[(size_t)(colBase + row) * 32 + bc];
    }

    for (int kc = 0; kc < 8; kc++) {
        __syncthreads();
#pragma unroll
        for (int it = 0; it < 2; it++) {
            int r = ar0 + it * 32;
            float4 v = pa[it];
            __nv_bfloat162 h01 = __floats2bfloat162_rn(v.x, v.y);
            __nv_bfloat162 h23 = __floats2bfloat162_rn(v.z, v.w);
            float2 f01 = __bfloat1622float2(h01);
            float2 f23 = __bfloat1622float2(h23);
            __nv_bfloat162 l01 = __floats2bfloat162_rn(v.x - f01.x, v.y - f01.y);
            __nv_bfloat162 l23 = __floats2bfloat162_rn(v.z - f23.x, v.w - f23.y);
            uint2 hp, lp;
            hp.x = *(uint32_t*)&h01; hp.y = *(uint32_t*)&h23;
            lp.x = *(uint32_t*)&l01; lp.y = *(uint32_t*)&l23;
            *(uint2*)&Ah[r * SA + ac4] = hp;
            *(uint2*)&Al[r * SA + ac4] = lp;
        }
#pragma unroll
        for (int it = 0; it < 2; it++) {
            int row = br + it * 64;
            *(uint4*)&Bh[row * SA + bc * 8] = pbh[it];
            *(uint4*)&Bl[row * SA + bc * 8] = pbl[it];
        }
        __syncthreads();

        if (kc < 7) {
            int k0 = (kc + 1) * 32;
            pa[0] = *(const float4*)(A + (size_t)(rowBase + ar0) * FIN + k0 + ac4);
            pa[1] = *(const float4*)(A + (size_t)(rowBase + ar0 + 32) * FIN + k0 + ac4);
#pragma unroll
            for (int it = 0; it < 2; it++) {
                int row = br + it * 64;
                pbh[it] = Wth4[(size_t)(colBase + row) * 32 + (kc + 1) * 4 + bc];
                pbl[it] = Wtl4[(size_t)(colBase + row) * 32 + (kc + 1) * 4 + bc];
            }
        }

#pragma unroll
        for (int ks = 0; ks < 2; ks++) {
            const uint32_t kb = (uint32_t)(ks * 16 * 2);
            uint32_t ah[2][4], al[2][4], bb[4][2];
#pragma unroll
            for (int mt = 0; mt < 2; mt++) {
                uint32_t ro = (uint32_t)((wm * 32 + mt * 16) * SA * 2);
                ldsm4(ah[mt][0], ah[mt][1], ah[mt][2], ah[mt][3], sAh + aoff + ro + kb);
                ldsm4(al[mt][0], al[mt][1], al[mt][2], al[mt][3], sAl + aoff + ro + kb);
            }
#pragma unroll
            for (int p = 0; p < 2; p++) {
                uint32_t ro = (uint32_t)((wn * 32 + p * 16) * SA * 2);
                ldsm4(bb[2 * p][0], bb[2 * p][1], bb[2 * p + 1][0], bb[2 * p + 1][1],
                      sBh + boff + ro + kb);
            }
#pragma unroll
            for (int mt = 0; mt < 2; mt++)
#pragma unroll
                for (int nt = 0; nt < 4; nt++) {
                    MMA_BF16(acc[mt][nt], ah[mt], bb[nt]);
                    MMA_BF16(acc[mt][nt], al[mt], bb[nt]);
                }
#pragma unroll
            for (int p = 0; p < 2; p++) {
                uint32_t ro = (uint32_t)((wn * 32 + p * 16) * SA * 2);
                ldsm4(bb[2 * p][0], bb[2 * p][1], bb[2 * p + 1][0], bb[2 * p + 1][1],
                      sBl + boff + ro + kb);
            }
#pragma unroll
            for (int mt = 0; mt < 2; mt++)
#pragma unroll
                for (int nt = 0; nt < 4; nt++)
                    MMA_BF16(acc[mt][nt], ah[mt], bb[nt]);
        }
    }

#pragma unroll
    for (int mt = 0; mt < 2; mt++) {
        int r0 = rowBase + wm * 32 + mt * 16 + g;
#pragma unroll
        for (int nt = 0; nt < 4; nt++) {
            int c0 = colBase + wn * 32 + nt * 8 + tg * 2;
            *(float2*)(g_buf + (size_t)r0 * OCOLS + c0) =
                make_float2(acc[mt][nt][0], acc[mt][nt][1]);
            *(float2*)(g_buf + (size_t)(r0 + 8) * OCOLS + c0) =
                make_float2(acc[mt][nt][2], acc[mt][nt][3]);
        }
    }

    // fused score
    {
        float ws[4][2], wd[4][2];
#pragma unroll
        for (int nt = 0; nt < 4; nt++)
#pragma unroll
            for (int j = 0; j < 2; j++) {
                int d = nt * 8 + tg * 2 + j;
                ws[nt][j] = attn_w[d];
                wd[nt][j] = attn_w[32 + d];
            }
        int hh = blockIdx.x * 4 + wn;
#pragma unroll
        for (int mt = 0; mt < 2; mt++)
#pragma unroll
            for (int rh = 0; rh < 2; rh++) {
                float as = 0.f, ad = 0.f;
#pragma unroll
                for (int nt = 0; nt < 4; nt++) {
                    as += acc[mt][nt][rh * 2] * ws[nt][0] + acc[mt][nt][rh * 2 + 1] * ws[nt][1];
                    ad += acc[mt][nt][rh * 2] * wd[nt][0] + acc[mt][nt][rh * 2 + 1] * wd[nt][1];
                }
                as += __shfl_xor_sync(0xffffffffu, as, 1);
                as += __shfl_xor_sync(0xffffffffu, as, 2);
                ad += __shfl_xor_sync(0xffffffffu, ad, 1);
                ad += __shfl_xor_sync(0xffffffffu, ad, 2);
                if (tg == 0) {
                    int m = rowBase + wm * 32 + mt * 16 + rh * 8 + g;
                    int b = m >> 10, i = m & 1023;
                    ssrc_buf[(size_t)(b * NH + hh) * N_ + i] = as;
                    sdst_buf[(size_t)(b * NH + hh) * N_ + i] = ad;
                }
            }
    }
}

// ---------------- kernel 2: MEGA — sort + scans + qscal + totals + write + serve ----------------
__device__ __forceinline__ void warp_passes_u(uint32_t& key, int k, int jmax, int tid) {
    for (int j = jmax; j > 0; j >>= 1) {
        uint32_t pk = __shfl_xor_sync(0xffffffffu, key, j);
        bool lower = ((tid & j) == 0);
        bool up = ((tid & k) == 0);
        bool keepmin = (lower == up);
        bool sw = keepmin ? (key > pk) : (key < pk);
        if (sw) key = pk;
    }
}

__global__ __launch_bounds__(1024) void mega_k(float* __restrict__ out) {
    __shared__ uint32_t su[1024];
    __shared__ float e1s[1024];
    __shared__ float e2s[1024];
    __shared__ float qsx[1024];
    __shared__ float qsy[1024];
    __shared__ int   qt[1024];
    __shared__ float wt[32], wo[32], wt2[32], wo2[32];
    __shared__ union {
        struct { float sc1[1025]; float sc2[1025]; } s;
        struct { float cb1[32][32]; float cb2[32][32]; } c;
    } u1;
    __shared__ union {
        float vs[1024];
        struct { float t1[32][33]; float t2[32][33]; } t;
    } u2;

    int bh = blockIdx.x;
    int b = bh >> 3, h = bh & 7;
    int tid = threadIdx.x;
    int w = tid >> 5, lane = tid & 31;

    // ---- A: sort ----
    float v0 = sdst_buf[(size_t)bh * N_ + tid];
    uint32_t u = __float_as_uint(v0);
    u = (u & 0x80000000u) ? ~u : (u | 0x80000000u);
    uint32_t key = (u & 0xFFFFFC00u) | (uint32_t)tid;

#pragma unroll
    for (int k = 2; k <= 32; k <<= 1) warp_passes_u(key, k, k >> 1, tid);
    su[tid] = key;
    __syncthreads();
    for (int k = 64; k <= 1024; k <<= 1) {
        for (int j = k >> 1; j >= 32; j >>= 1) {
            int ixj = tid ^ j;
            if (ixj > tid) {
                bool up = ((tid & k) == 0);
                uint32_t a = su[tid], c = su[ixj];
                bool sw = up ? (a > c) : (a < c);
                if (sw) { su[tid] = c; su[ixj] = a; }
            }
            __syncthreads();
        }
        key = su[tid];
        warp_passes_u(key, k, 16, tid);
        su[tid] = key;
        __syncthreads();
    }

    // ---- B: exponentials + scalar scans ----
    int idj = (int)(su[tid] & 1023u);
    float rv = sdst_buf[(size_t)bh * N_ + idj];
    u2.vs[tid] = rv;
    float x1 = __expf(rv);
    float x2 = __expf(0.2f * rv);
    e1s[tid] = x1; e2s[tid] = x2;

    float s2 = x2;
#pragma unroll
    for (int o = 1; o < 32; o <<= 1) {
        float y = __shfl_up_sync(0xffffffffu, s2, o);
        if (lane >= o) s2 += y;
    }
    if (lane == 31) wt2[w] = s2;
    float s1 = x1;
#pragma unroll
    for (int o = 1; o < 32; o <<= 1) {
        float y = __shfl_down_sync(0xffffffffu, s1, o);
        if (lane + o < 32) s1 += y;
    }
    if (lane == 0) wt[w] = s1;
    __syncthreads();
    if (w == 0) {
        float t = wt[lane];
        float ts = t;
#pragma unroll
        for (int o = 1; o < 32; o <<= 1) {
            float y = __shfl_down_sync(0xffffffffu, ts, o);
            if (lane + o < 32) ts += y;
        }
        wo[lane] = ts - t;
        float t2 = wt2[lane];
        float ps = t2;
#pragma unroll
        for (int o = 1; o < 32; o <<= 1) {
            float y = __shfl_up_sync(0xffffffffu, ps, o);
            if (lane >= o) ps += y;
        }
        wo2[lane] = ps - t2;
    }
    __syncthreads();
    u1.s.sc1[tid] = s1 + wo[w];
    u1.s.sc2[tid + 1] = s2 + wo2[w];
    if (tid == 0) {
        u1.s.sc1[1024] = 0.f;
        u1.s.sc2[0] = 0.f;
    }
    __syncthreads();

    // ---- C: per-query scalars (to smem) ----
    {
        float src = ssrc_buf[(size_t)bh * N_ + tid];
        float th = -src;
        int lo = 0, hi = 1024;
#pragma unroll
        for (int s = 0; s < 10; s++) {
            int mid = (lo + hi) >> 1;
            if (u2.vs[mid] < th) lo = mid + 1; else hi = mid;
        }
        int t = lo;
        float vmax = u2.vs[1023];
        float etop = src + vmax;
        float mM = (etop >= 0.f) ? etop : 0.2f * etop;
        float E1 = (t < 1024) ? __expf(src - mM) : 0.f;
        float E2 = (t > 0) ? __expf(0.2f * src - mM) : 0.f;
        float rden = 1.f / (E1 * u1.s.sc1[t] + E2 * u1.s.sc2[t]);
        qsx[tid] = E1 * rden;
        qsy[tid] = E2 * rden;
        qt[tid] = t;
    }
    __syncthreads();   // C done; u1/u2 regions may be repurposed

    // ---- D: vector chunk totals (warp w = chunk w, lane = d) ----
    const float* gb = g_buf + (size_t)b * N_ * OCOLS + h * ND;
    {
        float t1 = 0.f, t2v = 0.f;
#pragma unroll
        for (int half = 0; half < 2; half++) {
            float gv[16];
#pragma unroll
            for (int kk = 0; kk < 16; kk++) {
                int k = (w << 5) + half * 16 + kk;
                int j = (int)(su[k] & 1023u);
                gv[kk] = gb[(size_t)j * OCOLS + lane];
            }
#pragma unroll
            for (int kk = 0; kk < 16; kk++) {
                int k = (w << 5) + half * 16 + kk;
                t1 = fmaf(e1s[k], gv[kk], t1);
                t2v = fmaf(e2s[k], gv[kk], t2v);
            }
        }
        u2.t.t1[w][lane] = t1;
        u2.t.t2[w][lane] = t2v;
    }
    __syncthreads();
    {
        float a1 = u2.t.t1[lane][w];   // chunk = lane, d = w
        float a2 = u2.t.t2[lane][w];
        float inc1 = a1;
#pragma unroll
        for (int o = 1; o < 32; o <<= 1) {
            float y = __shfl_down_sync(0xffffffffu, inc1, o);
            if (lane + o < 32) inc1 += y;
        }
        float inc2 = a2;
#pragma unroll
        for (int o = 1; o < 32; o <<= 1) {
            float y = __shfl_up_sync(0xffffffffu, inc2, o);
            if (lane >= o) inc2 += y;
        }
        u1.c.cb1[lane][w] = inc1;          // inclusive suffix
        u1.c.cb2[lane][w] = inc2 - a2;     // exclusive prefix
    }
    __syncthreads();

    // ---- E: write S1/P2 (warp w walks chunk w serially, 2x16 prefetch) ----
    float* S1 = suf1_buf + (size_t)bh * ROWS * ND;
    float* P2 = pre2_buf + (size_t)bh * ROWS * ND;
    {
        float is1 = u1.c.cb1[w][lane];
        float p1 = 0.f;
        float r2 = u1.c.cb2[w][lane];
        if (w == 0) P2[lane] = 0.f;
#pragma unroll
        for (int half = 0; half < 2; half++) {
            int k0h = (w << 5) + half * 16;
            float gv[16];
#pragma unroll
            for (int kk = 0; kk < 16; kk++) {
                int j = (int)(su[k0h + kk] & 1023u);
                gv[kk] = gb[(size_t)j * OCOLS + lane];
            }
#pragma unroll
            for (int kk = 0; kk < 16; kk++) {
                int k = k0h + kk;
                S1[(size_t)k * ND + lane] = is1 - p1;
                p1 = fmaf(e1s[k], gv[kk], p1);
                r2 = fmaf(e2s[k], gv[kk], r2);
                P2[(size_t)(k + 1) * ND + lane] = r2;
            }
        }
        if (w == 31) S1[(size_t)1024 * ND + lane] = 0.f;
    }
    __syncthreads();   // S1/P2 visible block-wide

    // ---- F: serve queries (warp w -> queries 32w..32w+31) ----
    {
        float* orow = out + ((size_t)(b * N_) + (w << 5)) * OCOLS + h * ND + lane;
#pragma unroll 4
        for (int qq = 0; qq < 32; qq++) {
            int i = (w << 5) + qq;
            float sx = qsx[i];
            float sy = qsy[i];
            int t = qt[i];
            size_t base = (size_t)t * ND + lane;
            float o = sx * S1[base] + sy * P2[base];
            orow[(size_t)qq * OCOLS] = o;
        }
    }
}

// ---------------- launcher ----------------
extern "C" void kernel_launch(void* const* d_in, const int* in_sizes, int n_in,
                              void* d_out, int out_size) {
    const float* vertex = (const float*)d_in[0];
    const float* w_vert = (const float*)d_in[1];
    const float* attn_w = (const float*)d_in[2];
    float* out = (float*)d_out;

    trans_k<<<64, 256>>>(w_vert);
    dim3 gG(2, 128);
    gemm_mma_k<<<gG, 256>>>(vertex, attn_w);
    mega_k<<<NBH, 1024>>>(out);
}

// round 17
// speedup vs baseline: 1.1217x; 1.0792x over previous
#include <cuda_runtime.h>
#include <cuda_bf16.h>
#include <cstdint>

// Problem constants
#define B_    8
#define N_    1024
#define FIN   256
#define NH    8
#define ND    32
#define M_TOT (B_ * N_)      // 8192
#define NBH   (B_ * NH)      // 64
#define ROWS  1025
#define OCOLS (NH * ND)      // 256

// ---------------- scratch ----------------
__device__ float g_buf[M_TOT * OCOLS];
__device__ float ssrc_buf[NBH * N_];
__device__ float sdst_buf[NBH * N_];
__device__ float suf1_buf[NBH * ROWS * ND];
__device__ float pre2_buf[NBH * ROWS * ND];

// ---------------- helpers ----------------
#define MMA_BF16(d, a, b)                                                      \
    asm volatile("mma.sync.aligned.m16n8k16.row.col.f32.bf16.bf16.f32 "        \
        "{%0,%1,%2,%3}, {%4,%5,%6,%7}, {%8,%9}, {%0,%1,%2,%3};"                \
        : "+f"((d)[0]), "+f"((d)[1]), "+f"((d)[2]), "+f"((d)[3])               \
        : "r"((a)[0]), "r"((a)[1]), "r"((a)[2]), "r"((a)[3]),                  \
          "r"((b)[0]), "r"((b)[1]))

__device__ __forceinline__ void ldsm4(uint32_t& r0, uint32_t& r1, uint32_t& r2,
                                      uint32_t& r3, uint32_t a) {
    asm volatile("ldmatrix.sync.aligned.m8n8.x4.shared.b16 {%0,%1,%2,%3}, [%4];"
                 : "=r"(r0), "=r"(r1), "=r"(r2), "=r"(r3) : "r"(a));
}
__device__ __forceinline__ void ldsm4t(uint32_t& r0, uint32_t& r1, uint32_t& r2,
                                       uint32_t& r3, uint32_t a) {
    asm volatile("ldmatrix.sync.aligned.m8n8.x4.trans.shared.b16 {%0,%1,%2,%3}, [%4];"
                 : "=r"(r0), "=r"(r1), "=r"(r2), "=r"(r3) : "r"(a));
}

// ---------------- kernel 1: GEMM via HMMA; A n-major LDSM, B k-major LDSM.trans ----------------
#define SA 40
#define BSTR 136   // bf16 per B k-row (272 B: 4-bank stagger -> conflict-free ldsm.trans)
__global__ __launch_bounds__(256) void gemm_mma_k(const float* __restrict__ A,
                                                  const float* __restrict__ W,
                                                  const float* __restrict__ attn_w) {
    __shared__ __align__(16) __nv_bfloat16 Ah[64 * SA];
    __shared__ __align__(16) __nv_bfloat16 Al[64 * SA];
    __shared__ __align__(16) __nv_bfloat16 Bh[32 * BSTR];
    __shared__ __align__(16) __nv_bfloat16 Bl[32 * BSTR];

    const int tid = threadIdx.x;
    const int wid = tid >> 5, lane = tid & 31;
    const int wm = wid >> 2, wn = wid & 3;
    const int rowBase = blockIdx.y * 64;
    const int colBase = blockIdx.x * 128;
    const int g = lane >> 2, tg = lane & 3;

    // staging coords
    const int ar0 = tid >> 3, ac4 = (tid & 7) << 2;   // A: rows ar0, ar0+32
    const int bkr = tid >> 5, bn4 = (tid & 31) << 2;  // B: k-rows bkr + it*8, 4 n each

    const uint32_t sAh = (uint32_t)__cvta_generic_to_shared(Ah);
    const uint32_t sAl = (uint32_t)__cvta_generic_to_shared(Al);
    const uint32_t sBh = (uint32_t)__cvta_generic_to_shared(Bh);
    const uint32_t sBl = (uint32_t)__cvta_generic_to_shared(Bl);

    const uint32_t aoff = (uint32_t)(((lane & 15) * SA + ((lane >> 4) << 3)) * 2);
    // trans B: lane&15 = k-row, (lane>>4)*8 = n offset
    const uint32_t boffT = (uint32_t)(((lane & 15) * BSTR + ((lane >> 4) << 3)) * 2);

    float acc[2][4][4];
#pragma unroll
    for (int mt = 0; mt < 2; mt++)
#pragma unroll
        for (int nt = 0; nt < 4; nt++)
#pragma unroll
            for (int r = 0; r < 4; r++) acc[mt][nt][r] = 0.f;

    float4 pa[2], pw[4];
    pa[0] = *(const float4*)(A + (size_t)(rowBase + ar0) * FIN + ac4);
    pa[1] = *(const float4*)(A + (size_t)(rowBase + ar0 + 32) * FIN + ac4);
#pragma unroll
    for (int it = 0; it < 4; it++)
        pw[it] = *(const float4*)(W + (size_t)(bkr + it * 8) * OCOLS + colBase + bn4);

    for (int kc = 0; kc < 8; kc++) {
        __syncthreads();
        // stage A: packed bf16x2 hi/lo, 8-byte stores
#pragma unroll
        for (int it = 0; it < 2; it++) {
            int r = ar0 + it * 32;
            float4 v = pa[it];
            __nv_bfloat162 h01 = __floats2bfloat162_rn(v.x, v.y);
            __nv_bfloat162 h23 = __floats2bfloat162_rn(v.z, v.w);
            float2 f01 = __bfloat1622float2(h01);
            float2 f23 = __bfloat1622float2(h23);
            __nv_bfloat162 l01 = __floats2bfloat162_rn(v.x - f01.x, v.y - f01.y);
            __nv_bfloat162 l23 = __floats2bfloat162_rn(v.z - f23.x, v.w - f23.y);
            uint2 hp, lp;
            hp.x = *(uint32_t*)&h01; hp.y = *(uint32_t*)&h23;
            lp.x = *(uint32_t*)&l01; lp.y = *(uint32_t*)&l23;
            *(uint2*)&Ah[r * SA + ac4] = hp;
            *(uint2*)&Al[r * SA + ac4] = lp;
        }
        // stage B: fp32 W rows -> bf16 hi/lo, k-major, 8-byte stores
#pragma unroll
        for (int it = 0; it < 4; it++) {
            int kr = bkr + it * 8;
            float4 v = pw[it];
            __nv_bfloat162 h01 = __floats2bfloat162_rn(v.x, v.y);
            __nv_bfloat162 h23 = __floats2bfloat162_rn(v.z, v.w);
            float2 f01 = __bfloat1622float2(h01);
            float2 f23 = __bfloat1622float2(h23);
            __nv_bfloat162 l01 = __floats2bfloat162_rn(v.x - f01.x, v.y - f01.y);
            __nv_bfloat162 l23 = __floats2bfloat162_rn(v.z - f23.x, v.w - f23.y);
            uint2 hp, lp;
            hp.x = *(uint32_t*)&h01; hp.y = *(uint32_t*)&h23;
            lp.x = *(uint32_t*)&l01; lp.y = *(uint32_t*)&l23;
            *(uint2*)&Bh[kr * BSTR + bn4] = hp;
            *(uint2*)&Bl[kr * BSTR + bn4] = lp;
        }
        __syncthreads();

        if (kc < 7) {
            int k0 = (kc + 1) * 32;
            pa[0] = *(const float4*)(A + (size_t)(rowBase + ar0) * FIN + k0 + ac4);
            pa[1] = *(const float4*)(A + (size_t)(rowBase + ar0 + 32) * FIN + k0 + ac4);
#pragma unroll
            for (int it = 0; it < 4; it++)
                pw[it] = *(const float4*)(W + (size_t)(k0 + bkr + it * 8) * OCOLS + colBase + bn4);
        }

#pragma unroll
        for (int ks = 0; ks < 2; ks++) {
            uint32_t ah[2][4], al[2][4], bb[4][2];
#pragma unroll
            for (int mt = 0; mt < 2; mt++) {
                uint32_t ro = (uint32_t)((wm * 32 + mt * 16) * SA * 2) + (uint32_t)(ks * 32);
                ldsm4(ah[mt][0], ah[mt][1], ah[mt][2], ah[mt][3], sAh + aoff + ro);
                ldsm4(al[mt][0], al[mt][1], al[mt][2], al[mt][3], sAl + aoff + ro);
            }
            const uint32_t bro = (uint32_t)(ks * 16 * BSTR * 2);
#pragma unroll
            for (int p = 0; p < 2; p++) {
                uint32_t co = (uint32_t)((wn * 32 + p * 16) * 2);
                ldsm4t(bb[2 * p][0], bb[2 * p][1], bb[2 * p + 1][0], bb[2 * p + 1][1],
                       sBh + boffT + bro + co);
            }
#pragma unroll
            for (int mt = 0; mt < 2; mt++)
#pragma unroll
                for (int nt = 0; nt < 4; nt++) {
                    MMA_BF16(acc[mt][nt], ah[mt], bb[nt]);   // hi*hi
                    MMA_BF16(acc[mt][nt], al[mt], bb[nt]);   // lo*hi
                }
#pragma unroll
            for (int p = 0; p < 2; p++) {
                uint32_t co = (uint32_t)((wn * 32 + p * 16) * 2);
                ldsm4t(bb[2 * p][0], bb[2 * p][1], bb[2 * p + 1][0], bb[2 * p + 1][1],
                       sBl + boffT + bro + co);
            }
#pragma unroll
            for (int mt = 0; mt < 2; mt++)
#pragma unroll
                for (int nt = 0; nt < 4; nt++)
                    MMA_BF16(acc[mt][nt], ah[mt], bb[nt]);   // hi*lo
        }
    }

#pragma unroll
    for (int mt = 0; mt < 2; mt++) {
        int r0 = rowBase + wm * 32 + mt * 16 + g;
#pragma unroll
        for (int nt = 0; nt < 4; nt++) {
            int c0 = colBase + wn * 32 + nt * 8 + tg * 2;
            *(float2*)(g_buf + (size_t)r0 * OCOLS + c0) =
                make_float2(acc[mt][nt][0], acc[mt][nt][1]);
            *(float2*)(g_buf + (size_t)(r0 + 8) * OCOLS + c0) =
                make_float2(acc[mt][nt][2], acc[mt][nt][3]);
        }
    }

    // fused score
    {
        float ws[4][2], wd[4][2];
#pragma unroll
        for (int nt = 0; nt < 4; nt++)
#pragma unroll
            for (int j = 0; j < 2; j++) {
                int d = nt * 8 + tg * 2 + j;
                ws[nt][j] = attn_w[d];
                wd[nt][j] = attn_w[32 + d];
            }
        int hh = blockIdx.x * 4 + wn;
#pragma unroll
        for (int mt = 0; mt < 2; mt++)
#pragma unroll
            for (int rh = 0; rh < 2; rh++) {
                float as = 0.f, ad = 0.f;
#pragma unroll
                for (int nt = 0; nt < 4; nt++) {
                    as += acc[mt][nt][rh * 2] * ws[nt][0] + acc[mt][nt][rh * 2 + 1] * ws[nt][1];
                    ad += acc[mt][nt][rh * 2] * wd[nt][0] + acc[mt][nt][rh * 2 + 1] * wd[nt][1];
                }
                as += __shfl_xor_sync(0xffffffffu, as, 1);
                as += __shfl_xor_sync(0xffffffffu, as, 2);
                ad += __shfl_xor_sync(0xffffffffu, ad, 1);
                ad += __shfl_xor_sync(0xffffffffu, ad, 2);
                if (tg == 0) {
                    int m = rowBase + wm * 32 + mt * 16 + rh * 8 + g;
                    int b = m >> 10, i = m & 1023;
                    ssrc_buf[(size_t)(b * NH + hh) * N_ + i] = as;
                    sdst_buf[(size_t)(b * NH + hh) * N_ + i] = ad;
                }
            }
    }
}

// ---------------- kernel 2: MEGA — sort + scans + qscal + totals + write + serve ----------------
__device__ __forceinline__ void warp_passes_u(uint32_t& key, int k, int jmax, int tid) {
    for (int j = jmax; j > 0; j >>= 1) {
        uint32_t pk = __shfl_xor_sync(0xffffffffu, key, j);
        bool lower = ((tid & j) == 0);
        bool up = ((tid & k) == 0);
        bool keepmin = (lower == up);
        bool sw = keepmin ? (key > pk) : (key < pk);
        if (sw) key = pk;
    }
}

__global__ __launch_bounds__(1024) void mega_k(float* __restrict__ out) {
    __shared__ uint32_t su[1024];
    __shared__ float e1s[1024];
    __shared__ float e2s[1024];
    __shared__ float qsx[1024];
    __shared__ float qsy[1024];
    __shared__ int   qt[1024];
    __shared__ float wt[32], wo[32], wt2[32], wo2[32];
    __shared__ union {
        struct { float sc1[1025]; float sc2[1025]; } s;
        struct { float cb1[32][32]; float cb2[32][32]; } c;
    } u1;
    __shared__ union {
        float vs[1024];
        struct { float t1[32][33]; float t2[32][33]; } t;
    } u2;

    int bh = blockIdx.x;
    int b = bh >> 3, h = bh & 7;
    int tid = threadIdx.x;
    int w = tid >> 5, lane = tid & 31;

    // ---- A: sort ----
    float v0 = sdst_buf[(size_t)bh * N_ + tid];
    uint32_t u = __float_as_uint(v0);
    u = (u & 0x80000000u) ? ~u : (u | 0x80000000u);
    uint32_t key = (u & 0xFFFFFC00u) | (uint32_t)tid;

#pragma unroll
    for (int k = 2; k <= 32; k <<= 1) warp_passes_u(key, k, k >> 1, tid);
    su[tid] = key;
    __syncthreads();
    for (int k = 64; k <= 1024; k <<= 1) {
        for (int j = k >> 1; j >= 32; j >>= 1) {
            int ixj = tid ^ j;
            if (ixj > tid) {
                bool up = ((tid & k) == 0);
                uint32_t a = su[tid], c = su[ixj];
                bool sw = up ? (a > c) : (a < c);
                if (sw) { su[tid] = c; su[ixj] = a; }
            }
            __syncthreads();
        }
        key = su[tid];
        warp_passes_u(key, k, 16, tid);
        su[tid] = key;
        __syncthreads();
    }

    // ---- B: exponentials + scalar scans ----
    int idj = (int)(su[tid] & 1023u);
    float rv = sdst_buf[(size_t)bh * N_ + idj];
    u2.vs[tid] = rv;
    float x1 = __expf(rv);
    float x2 = __expf(0.2f * rv);
    e1s[tid] = x1; e2s[tid] = x2;

    float s2 = x2;
#pragma unroll
    for (int o = 1; o < 32; o <<= 1) {
        float y = __shfl_up_sync(0xffffffffu, s2, o);
        if (lane >= o) s2 += y;
    }
    if (lane == 31) wt2[w] = s2;
    float s1 = x1;
#pragma unroll
    for (int o = 1; o < 32; o <<= 1) {
        float y = __shfl_down_sync(0xffffffffu, s1, o);
        if (lane + o < 32) s1 += y;
    }
    if (lane == 0) wt[w] = s1;
    __syncthreads();
    if (w == 0) {
        float t = wt[lane];
        float ts = t;
#pragma unroll
        for (int o = 1; o < 32; o <<= 1) {
            float y = __shfl_down_sync(0xffffffffu, ts, o);
            if (lane + o < 32) ts += y;
        }
        wo[lane] = ts - t;
        float t2 = wt2[lane];
        float ps = t2;
#pragma unroll
        for (int o = 1; o < 32; o <<= 1) {
            float y = __shfl_up_sync(0xffffffffu, ps, o);
            if (lane >= o) ps += y;
        }
        wo2[lane] = ps - t2;
    }
    __syncthreads();
    u1.s.sc1[tid] = s1 + wo[w];
    u1.s.sc2[tid + 1] = s2 + wo2[w];
    if (tid == 0) {
        u1.s.sc1[1024] = 0.f;
        u1.s.sc2[0] = 0.f;
    }
    __syncthreads();

    // ---- C: per-query scalars (to smem) ----
    {
        float src = ssrc_buf[(size_t)bh * N_ + tid];
        float th = -src;
        int lo = 0, hi = 1024;
#pragma unroll
        for (int s = 0; s < 10; s++) {
            int mid = (lo + hi) >> 1;
            if (u2.vs[mid] < th) lo = mid + 1; else hi = mid;
        }
        int t = lo;
        float vmax = u2.vs[1023];
        float etop = src + vmax;
        float mM = (etop >= 0.f) ? etop : 0.2f * etop;
        float E1 = (t < 1024) ? __expf(src - mM) : 0.f;
        float E2 = (t > 0) ? __expf(0.2f * src - mM) : 0.f;
        float rden = 1.f / (E1 * u1.s.sc1[t] + E2 * u1.s.sc2[t]);
        qsx[tid] = E1 * rden;
        qsy[tid] = E2 * rden;
        qt[tid] = t;
    }
    __syncthreads();

    // ---- D: vector chunk totals ----
    const float* gb = g_buf + (size_t)b * N_ * OCOLS + h * ND;
    {
        float t1 = 0.f, t2v = 0.f;
#pragma unroll
        for (int half = 0; half < 2; half++) {
            float gv[16];
#pragma unroll
            for (int kk = 0; kk < 16; kk++) {
                int k = (w << 5) + half * 16 + kk;
                int j = (int)(su[k] & 1023u);
                gv[kk] = gb[(size_t)j * OCOLS + lane];
            }
#pragma unroll
            for (int kk = 0; kk < 16; kk++) {
                int k = (w << 5) + half * 16 + kk;
                t1 = fmaf(e1s[k], gv[kk], t1);
                t2v = fmaf(e2s[k], gv[kk], t2v);
            }
        }
        u2.t.t1[w][lane] = t1;
        u2.t.t2[w][lane] = t2v;
    }
    __syncthreads();
    {
        float a1 = u2.t.t1[lane][w];
        float a2 = u2.t.t2[lane][w];
        float inc1 = a1;
#pragma unroll
        for (int o = 1; o < 32; o <<= 1) {
            float y = __shfl_down_sync(0xffffffffu, inc1, o);
            if (lane + o < 32) inc1 += y;
        }
        float inc2 = a2;
#pragma unroll
        for (int o = 1; o < 32; o <<= 1) {
            float y = __shfl_up_sync(0xffffffffu, inc2, o);
            if (lane >= o) inc2 += y;
        }
        u1.c.cb1[lane][w] = inc1;
        u1.c.cb2[lane][w] = inc2 - a2;
    }
    __syncthreads();

    // ---- E: write S1/P2 ----
    float* S1 = suf1_buf + (size_t)bh * ROWS * ND;
    float* P2 = pre2_buf + (size_t)bh * ROWS * ND;
    {
        float is1 = u1.c.cb1[w][lane];
        float p1 = 0.f;
        float r2 = u1.c.cb2[w][lane];
        if (w == 0) P2[lane] = 0.f;
#pragma unroll
        for (int half = 0; half < 2; half++) {
            int k0h = (w << 5) + half * 16;
            float gv[16];
#pragma unroll
            for (int kk = 0; kk < 16; kk++) {
                int j = (int)(su[k0h + kk] & 1023u);
                gv[kk] = gb[(size_t)j * OCOLS + lane];
            }
#pragma unroll
            for (int kk = 0; kk < 16; kk++) {
                int k = k0h + kk;
                S1[(size_t)k * ND + lane] = is1 - p1;
                p1 = fmaf(e1s[k], gv[kk], p1);
                r2 = fmaf(e2s[k], gv[kk], r2);
                P2[(size_t)(k + 1) * ND + lane] = r2;
            }
        }
        if (w == 31) S1[(size_t)1024 * ND + lane] = 0.f;
    }
    __syncthreads();

    // ---- F: serve queries ----
    {
        float* orow = out + ((size_t)(b * N_) + (w << 5)) * OCOLS + h * ND + lane;
#pragma unroll 4
        for (int qq = 0; qq < 32; qq++) {
            int i = (w << 5) + qq;
            float sx = qsx[i];
            float sy = qsy[i];
            int t = qt[i];
            size_t base = (size_t)t * ND + lane;
            float o = sx * S1[base] + sy * P2[base];
            orow[(size_t)qq * OCOLS] = o;
        }
    }
}

// ---------------- launcher ----------------
extern "C" void kernel_launch(void* const* d_in, const int* in_sizes, int n_in,
                              void* d_out, int out_size) {
    const float* vertex = (const float*)d_in[0];
    const float* w_vert = (const float*)d_in[1];
    const float* attn_w = (const float*)d_in[2];
    float* out = (float*)d_out;

    dim3 gG(2, 128);
    gemm_mma_k<<<gG, 256>>>(vertex, w_vert, attn_w);
    mega_k<<<NBH, 1024>>>(out);
}